// round 1
// baseline (speedup 1.0000x reference)
#include <cuda_runtime.h>
#include <math.h>

// ---------------- problem constants ----------------
#define B_     2
#define L_     1024
#define T_     2048            // B_*L_
#define DM     1024            // d_model
#define DIN    2048            // d_inner
#define NH     32              // nheads
#define HD     64              // headdim
#define DS     128             // d_state
#define CONVD  2304            // DIN + 2*DS
#define DPROJ  4384            // 2*DIN + 2*DS + NH
#define INTER  2752
#define EPSF   1e-6f

// ---------------- scratch (device globals; no allocation allowed) ----------------
__device__ float g_xn  [(size_t)T_*DM];     // rmsnorm(hidden)
__device__ float g_zx  [(size_t)T_*DPROJ];  // in_proj output
__device__ float g_cv  [(size_t)T_*CONVD];  // conv+silu output
__device__ float g_y   [(size_t)T_*DIN];    // scan output
__device__ float g_yn  [(size_t)T_*DIN];    // gated-norm output
__device__ float g_x2  [(size_t)T_*DM];     // residual after mixer
__device__ float g_hn  [(size_t)T_*DM];     // post-norm
__device__ float g_gate[(size_t)T_*INTER];
__device__ float g_up  [(size_t)T_*INTER];

// ---------------- helpers ----------------
__device__ __forceinline__ float siluf(float x) {
    return x / (1.f + __expf(-x));
}

__device__ __forceinline__ float block_reduce_sum(float v) {
    __shared__ float sh[32];
    int lane = threadIdx.x & 31, w = threadIdx.x >> 5;
    #pragma unroll
    for (int o = 16; o; o >>= 1) v += __shfl_xor_sync(0xffffffffu, v, o);
    if (lane == 0) sh[w] = v;
    __syncthreads();
    int nw = blockDim.x >> 5;
    v = (threadIdx.x < (unsigned)nw) ? sh[threadIdx.x] : 0.f;
    if (w == 0) {
        #pragma unroll
        for (int o = 16; o; o >>= 1) v += __shfl_xor_sync(0xffffffffu, v, o);
        if (lane == 0) sh[0] = v;
    }
    __syncthreads();
    return sh[0];
}

// ---------------- rmsnorm over D=1024 (one block per row, 256 thr, float4) ----------------
__global__ void rmsnorm1024_k(const float* __restrict__ x, const float* __restrict__ w,
                              float* __restrict__ o) {
    int row = blockIdx.x;
    int i = threadIdx.x * 4;
    const float4 v = *(const float4*)(x + (size_t)row * DM + i);
    float ss = v.x*v.x + v.y*v.y + v.z*v.z + v.w*v.w;
    ss = block_reduce_sum(ss);
    float sc = rsqrtf(ss * (1.f / DM) + EPSF);
    float4 wv = *(const float4*)(w + i);
    float4 r;
    r.x = v.x * sc * wv.x; r.y = v.y * sc * wv.y;
    r.z = v.z * sc * wv.z; r.w = v.w * sc * wv.w;
    *(float4*)(o + (size_t)row * DM + i) = r;
}

// ---------------- gated rmsnorm: out = rmsnorm(y * silu(z)) * w, D=2048 ----------------
__global__ void gated_norm_k(const float* __restrict__ y, const float* __restrict__ zx,
                             const float* __restrict__ w, float* __restrict__ o) {
    int row = blockIdx.x;
    float vals[8];
    float ss = 0.f;
    #pragma unroll
    for (int c = 0; c < 2; c++) {
        int i = threadIdx.x * 4 + c * 1024;
        float4 yv = *(const float4*)(y  + (size_t)row * DIN   + i);
        float4 zv = *(const float4*)(zx + (size_t)row * DPROJ + i);
        float a = yv.x * siluf(zv.x);
        float b = yv.y * siluf(zv.y);
        float cc = yv.z * siluf(zv.z);
        float d = yv.w * siluf(zv.w);
        vals[c*4+0]=a; vals[c*4+1]=b; vals[c*4+2]=cc; vals[c*4+3]=d;
        ss += a*a + b*b + cc*cc + d*d;
    }
    ss = block_reduce_sum(ss);
    float sc = rsqrtf(ss * (1.f / DIN) + EPSF);
    #pragma unroll
    for (int c = 0; c < 2; c++) {
        int i = threadIdx.x * 4 + c * 1024;
        float4 wv = *(const float4*)(w + i);
        float4 r;
        r.x = vals[c*4+0] * sc * wv.x; r.y = vals[c*4+1] * sc * wv.y;
        r.z = vals[c*4+2] * sc * wv.z; r.w = vals[c*4+3] * sc * wv.w;
        *(float4*)(o + (size_t)row * DIN + i) = r;
    }
}

// ---------------- causal depthwise conv (width 4) + bias + silu ----------------
__global__ void conv_k(const float* __restrict__ zx, const float* __restrict__ w,
                       const float* __restrict__ bias, float* __restrict__ out) {
    int idx = blockIdx.x * blockDim.x + threadIdx.x;
    if (idx >= T_ * CONVD) return;
    int c   = idx % CONVD;
    int tok = idx / CONVD;
    int l   = tok % L_;
    const float* base = zx + (size_t)tok * DPROJ + DIN + c;
    float w0 = w[c*4+0], w1 = w[c*4+1], w2 = w[c*4+2], w3 = w[c*4+3];
    float acc = bias[c];
    if (l >= 3) acc += base[-(ptrdiff_t)3*DPROJ] * w0;
    if (l >= 2) acc += base[-(ptrdiff_t)2*DPROJ] * w1;
    if (l >= 1) acc += base[-(ptrdiff_t)1*DPROJ] * w2;
    acc += base[0] * w3;
    out[idx] = siluf(acc);
}

// ---------------- selective scan ----------------
// grid = B_*NH*2 (p split in halves of 32); 256 threads.
// thread: p_local = tid>>3 (0..31), n chunk = (tid&7)*16 .. +16. 16 states in regs.
__device__ __forceinline__ void scan_load(const float* Bp, const float* Cp,
                                          const float* dp, const float* xp,
                                          int t, float4* Bo, float4* Co,
                                          float& dto, float& xo) {
    size_t roff = (size_t)t * CONVD;
    #pragma unroll
    for (int i = 0; i < 4; i++) {
        Bo[i] = *(const float4*)(Bp + roff + i*4);
        Co[i] = *(const float4*)(Cp + roff + i*4);
    }
    dto = dp[(size_t)t * DPROJ];
    xo  = xp[roff];
}

__global__ void __launch_bounds__(256) scan_k(const float* __restrict__ cv,
                                              const float* __restrict__ zx,
                                              const float* __restrict__ dt_bias,
                                              const float* __restrict__ A_log,
                                              const float* __restrict__ Dv,
                                              float* __restrict__ y) {
    int bid = blockIdx.x;
    int ps  = bid & 1;
    int h   = (bid >> 1) & 31;
    int b   = bid >> 6;
    int tid = threadIdx.x;
    int pl  = tid >> 3;
    int p   = ps * 32 + pl;
    int nb  = (tid & 7) << 4;

    float Ah   = -__expf(A_log[h]);
    float Dh   = Dv[h];
    float bias = dt_bias[h];

    const float* xptr = cv + (size_t)b * L_ * CONVD + h * HD + p;
    const float* Bptr = cv + (size_t)b * L_ * CONVD + DIN + nb;
    const float* Cptr = cv + (size_t)b * L_ * CONVD + DIN + DS + nb;
    const float* dptr = zx + (size_t)b * L_ * DPROJ + (DPROJ - NH) + h;
    float*       yptr = y  + (size_t)b * L_ * DIN + h * HD + p;

    float hs[16];
    #pragma unroll
    for (int i = 0; i < 16; i++) hs[i] = 0.f;

    float4 Bf[4], Cf[4];
    float dtr, xv;
    scan_load(Bptr, Cptr, dptr, xptr, 0, Bf, Cf, dtr, xv);

    for (int t = 0; t < L_; t++) {
        float4 Bn2[4], Cn2[4];
        float dtn, xn2;
        int tn = (t + 1 < L_) ? (t + 1) : t;
        scan_load(Bptr, Cptr, dptr, xptr, tn, Bn2, Cn2, dtn, xn2);

        float v   = dtr + bias;
        float dt  = (v > 20.f) ? v : log1pf(__expf(v));
        float dA  = __expf(dt * Ah);
        float dtx = dt * xv;

        const float* bb = reinterpret_cast<const float*>(Bf);
        const float* cc = reinterpret_cast<const float*>(Cf);
        float yp = 0.f;
        #pragma unroll
        for (int i = 0; i < 16; i++) {
            hs[i] = fmaf(hs[i], dA, dtx * bb[i]);
            yp    = fmaf(hs[i], cc[i], yp);
        }
        yp += __shfl_xor_sync(0xffffffffu, yp, 1);
        yp += __shfl_xor_sync(0xffffffffu, yp, 2);
        yp += __shfl_xor_sync(0xffffffffu, yp, 4);
        if ((tid & 7) == 0)
            yptr[(size_t)t * DIN] = yp + Dh * xv;

        #pragma unroll
        for (int i = 0; i < 4; i++) { Bf[i] = Bn2[i]; Cf[i] = Cn2[i]; }
        dtr = dtn; xv = xn2;
    }
}

// ---------------- fp32 SIMT GEMM:  C[M,N] = A[M,K] * B[N,K]^T (+ Res) ----------------
// 128x128 block tile, BK=16, 256 threads, 8x8 per thread, register prefetch.
// Requires: M % 128 == 0, K % 16 == 0, N % 4 == 0 (N tiles guarded).
__global__ void __launch_bounds__(256) gemm_nt(const float* __restrict__ A,
                                               const float* __restrict__ Bm,
                                               const float* __restrict__ Res,
                                               float* __restrict__ C,
                                               int M, int N, int K) {
    __shared__ float As[16][132];
    __shared__ float Bs[16][132];

    int tid = threadIdx.x;
    int bm = blockIdx.y, bn = blockIdx.x;
    int tx = tid & 15, ty = tid >> 4;

    int lrow = tid >> 2;   // 0..63
    int lq   = tid & 3;    // 0..3 (k quad)

    const float* Ap = A + (size_t)(bm * 128 + lrow) * K + lq * 4;
    int n0 = bn * 128 + lrow;
    int n1 = n0 + 64;
    const float* Bp0 = Bm + (size_t)n0 * K + lq * 4;
    const float* Bp1 = Bm + (size_t)n1 * K + lq * 4;
    bool bv0 = n0 < N, bv1 = n1 < N;

    float acc[8][8];
    #pragma unroll
    for (int i = 0; i < 8; i++)
        #pragma unroll
        for (int j = 0; j < 8; j++) acc[i][j] = 0.f;

    const float4 fz = make_float4(0.f, 0.f, 0.f, 0.f);
    int nk = K >> 4;

    float4 pa0 = *(const float4*)(Ap);
    float4 pa1 = *(const float4*)(Ap + (size_t)64 * K);
    float4 pb0 = bv0 ? *(const float4*)(Bp0) : fz;
    float4 pb1 = bv1 ? *(const float4*)(Bp1) : fz;

    for (int kt = 0; kt < nk; kt++) {
        As[lq*4+0][lrow]    = pa0.x; As[lq*4+1][lrow]    = pa0.y;
        As[lq*4+2][lrow]    = pa0.z; As[lq*4+3][lrow]    = pa0.w;
        As[lq*4+0][lrow+64] = pa1.x; As[lq*4+1][lrow+64] = pa1.y;
        As[lq*4+2][lrow+64] = pa1.z; As[lq*4+3][lrow+64] = pa1.w;
        Bs[lq*4+0][lrow]    = pb0.x; Bs[lq*4+1][lrow]    = pb0.y;
        Bs[lq*4+2][lrow]    = pb0.z; Bs[lq*4+3][lrow]    = pb0.w;
        Bs[lq*4+0][lrow+64] = pb1.x; Bs[lq*4+1][lrow+64] = pb1.y;
        Bs[lq*4+2][lrow+64] = pb1.z; Bs[lq*4+3][lrow+64] = pb1.w;
        __syncthreads();

        if (kt + 1 < nk) {
            const float* a = Ap + (size_t)(kt + 1) * 16;
            pa0 = *(const float4*)(a);
            pa1 = *(const float4*)(a + (size_t)64 * K);
            pb0 = bv0 ? *(const float4*)(Bp0 + (size_t)(kt + 1) * 16) : fz;
            pb1 = bv1 ? *(const float4*)(Bp1 + (size_t)(kt + 1) * 16) : fz;
        }

        #pragma unroll
        for (int k = 0; k < 16; k++) {
            float4 a0 = *(const float4*)&As[k][ty * 4];
            float4 a1 = *(const float4*)&As[k][ty * 4 + 64];
            float4 b0 = *(const float4*)&Bs[k][tx * 4];
            float4 b1 = *(const float4*)&Bs[k][tx * 4 + 64];
            float av[8] = {a0.x, a0.y, a0.z, a0.w, a1.x, a1.y, a1.z, a1.w};
            float bw[8] = {b0.x, b0.y, b0.z, b0.w, b1.x, b1.y, b1.z, b1.w};
            #pragma unroll
            for (int i = 0; i < 8; i++)
                #pragma unroll
                for (int j = 0; j < 8; j++)
                    acc[i][j] = fmaf(av[i], bw[j], acc[i][j]);
        }
        __syncthreads();
    }

    #pragma unroll
    for (int i = 0; i < 8; i++) {
        int row = bm * 128 + ((i < 4) ? (ty * 4 + i) : (64 + ty * 4 + (i - 4)));
        float* Cr = C + (size_t)row * N;
        #pragma unroll
        for (int jh = 0; jh < 2; jh++) {
            int col = bn * 128 + tx * 4 + jh * 64;
            if (col < N) {
                float4 vv;
                vv.x = acc[i][jh*4+0]; vv.y = acc[i][jh*4+1];
                vv.z = acc[i][jh*4+2]; vv.w = acc[i][jh*4+3];
                if (Res) {
                    float4 r = *(const float4*)(Res + (size_t)row * N + col);
                    vv.x += r.x; vv.y += r.y; vv.z += r.z; vv.w += r.w;
                }
                *(float4*)(Cr + col) = vv;
            }
        }
    }
}

// ---------------- silu(gate) * up, in place into gate ----------------
__global__ void act_k(float* __restrict__ g, const float* __restrict__ u, int n) {
    int idx = blockIdx.x * blockDim.x + threadIdx.x;
    if (idx >= n) return;
    float x = g[idx];
    g[idx] = siluf(x) * u[idx];
}

// ---------------- host launcher ----------------
extern "C" void kernel_launch(void* const* d_in, const int* in_sizes, int n_in,
                              void* d_out, int out_size) {
    const float* hid        = (const float*)d_in[0];
    const float* norm_w     = (const float*)d_in[1];
    const float* in_proj_w  = (const float*)d_in[2];
    const float* conv_w     = (const float*)d_in[3];
    const float* conv_b     = (const float*)d_in[4];
    const float* dt_bias    = (const float*)d_in[5];
    const float* A_log      = (const float*)d_in[6];
    const float* Dv         = (const float*)d_in[7];
    const float* ssm_norm_w = (const float*)d_in[8];
    const float* out_proj_w = (const float*)d_in[9];
    const float* post_norm_w= (const float*)d_in[10];
    const float* gate_w     = (const float*)d_in[11];
    const float* up_w       = (const float*)d_in[12];
    const float* down_w     = (const float*)d_in[13];
    float* out = (float*)d_out;

    float *p_xn, *p_zx, *p_cv, *p_y, *p_yn, *p_x2, *p_hn, *p_gate, *p_up;
    cudaGetSymbolAddress((void**)&p_xn,   g_xn);
    cudaGetSymbolAddress((void**)&p_zx,   g_zx);
    cudaGetSymbolAddress((void**)&p_cv,   g_cv);
    cudaGetSymbolAddress((void**)&p_y,    g_y);
    cudaGetSymbolAddress((void**)&p_yn,   g_yn);
    cudaGetSymbolAddress((void**)&p_x2,   g_x2);
    cudaGetSymbolAddress((void**)&p_hn,   g_hn);
    cudaGetSymbolAddress((void**)&p_gate, g_gate);
    cudaGetSymbolAddress((void**)&p_up,   g_up);

    // 1. pre-norm
    rmsnorm1024_k<<<T_, 256>>>(hid, norm_w, p_xn);
    // 2. in_proj: [2048,4384] = xn @ W^T
    gemm_nt<<<dim3(35, 16), 256>>>(p_xn, in_proj_w, nullptr, p_zx, T_, DPROJ, DM);
    // 3. conv + silu
    conv_k<<<(T_ * CONVD + 255) / 256, 256>>>(p_zx, conv_w, conv_b, p_cv);
    // 4. selective scan
    scan_k<<<B_ * NH * 2, 256>>>(p_cv, p_zx, dt_bias, A_log, Dv, p_y);
    // 5. gated rmsnorm
    gated_norm_k<<<T_, 256>>>(p_y, p_zx, ssm_norm_w, p_yn);
    // 6. out_proj + residual (res = hidden_states)
    gemm_nt<<<dim3(8, 16), 256>>>(p_yn, out_proj_w, hid, p_x2, T_, DM, DIN);
    // 7. post-norm
    rmsnorm1024_k<<<T_, 256>>>(p_x2, post_norm_w, p_hn);
    // 8/9. gate & up projections
    gemm_nt<<<dim3(22, 16), 256>>>(p_hn, gate_w, nullptr, p_gate, T_, INTER, DM);
    gemm_nt<<<dim3(22, 16), 256>>>(p_hn, up_w, nullptr, p_up, T_, INTER, DM);
    // 10. silu(gate) * up
    act_k<<<(T_ * INTER + 255) / 256, 256>>>(p_gate, p_up, T_ * INTER);
    // 11. down projection + residual -> output
    gemm_nt<<<dim3(8, 16), 256>>>(p_gate, down_w, p_x2, out, T_, DM, INTER);
}

// round 2
// speedup vs baseline: 1.0239x; 1.0239x over previous
#include <cuda_runtime.h>
#include <math.h>

// ---------------- problem constants ----------------
#define B_     2
#define L_     1024
#define T_     2048            // B_*L_
#define DM     1024            // d_model
#define DIN    2048            // d_inner
#define NH     32              // nheads
#define HD     64              // headdim
#define DS     128             // d_state
#define CONVD  2304            // DIN + 2*DS
#define DPROJ  4384            // 2*DIN + 2*DS + NH
#define INTER  2752
#define EPSF   1e-6f
#define TS     8               // scan time-chunk (double-buffered staging)

// ---------------- scratch (device globals; no allocation allowed) ----------------
__device__ float g_xn  [(size_t)T_*DM];     // rmsnorm(hidden)
__device__ float g_zx  [(size_t)T_*DPROJ];  // in_proj output
__device__ float g_cv  [(size_t)T_*CONVD];  // conv+silu output
__device__ float g_y   [(size_t)T_*DIN];    // scan output
__device__ float g_yn  [(size_t)T_*DIN];    // gated-norm output
__device__ float g_x2  [(size_t)T_*DM];     // residual after mixer
__device__ float g_hn  [(size_t)T_*DM];     // post-norm
__device__ float g_gate[(size_t)T_*INTER];
__device__ float g_up  [(size_t)T_*INTER];

// ---------------- helpers ----------------
__device__ __forceinline__ float siluf(float x) {
    return x / (1.f + __expf(-x));
}

__device__ __forceinline__ float block_reduce_sum(float v) {
    __shared__ float sh[32];
    int lane = threadIdx.x & 31, w = threadIdx.x >> 5;
    #pragma unroll
    for (int o = 16; o; o >>= 1) v += __shfl_xor_sync(0xffffffffu, v, o);
    if (lane == 0) sh[w] = v;
    __syncthreads();
    int nw = blockDim.x >> 5;
    v = (threadIdx.x < (unsigned)nw) ? sh[threadIdx.x] : 0.f;
    if (w == 0) {
        #pragma unroll
        for (int o = 16; o; o >>= 1) v += __shfl_xor_sync(0xffffffffu, v, o);
        if (lane == 0) sh[0] = v;
    }
    __syncthreads();
    return sh[0];
}

// ---------------- rmsnorm over D=1024 (one block per row, 256 thr, float4) ----------------
__global__ void rmsnorm1024_k(const float* __restrict__ x, const float* __restrict__ w,
                              float* __restrict__ o) {
    int row = blockIdx.x;
    int i = threadIdx.x * 4;
    const float4 v = *(const float4*)(x + (size_t)row * DM + i);
    float ss = v.x*v.x + v.y*v.y + v.z*v.z + v.w*v.w;
    ss = block_reduce_sum(ss);
    float sc = rsqrtf(ss * (1.f / DM) + EPSF);
    float4 wv = *(const float4*)(w + i);
    float4 r;
    r.x = v.x * sc * wv.x; r.y = v.y * sc * wv.y;
    r.z = v.z * sc * wv.z; r.w = v.w * sc * wv.w;
    *(float4*)(o + (size_t)row * DM + i) = r;
}

// ---------------- gated rmsnorm: out = rmsnorm(y * silu(z)) * w, D=2048 ----------------
__global__ void gated_norm_k(const float* __restrict__ y, const float* __restrict__ zx,
                             const float* __restrict__ w, float* __restrict__ o) {
    int row = blockIdx.x;
    float vals[8];
    float ss = 0.f;
    #pragma unroll
    for (int c = 0; c < 2; c++) {
        int i = threadIdx.x * 4 + c * 1024;
        float4 yv = *(const float4*)(y  + (size_t)row * DIN   + i);
        float4 zv = *(const float4*)(zx + (size_t)row * DPROJ + i);
        float a = yv.x * siluf(zv.x);
        float b = yv.y * siluf(zv.y);
        float cc = yv.z * siluf(zv.z);
        float d = yv.w * siluf(zv.w);
        vals[c*4+0]=a; vals[c*4+1]=b; vals[c*4+2]=cc; vals[c*4+3]=d;
        ss += a*a + b*b + cc*cc + d*d;
    }
    ss = block_reduce_sum(ss);
    float sc = rsqrtf(ss * (1.f / DIN) + EPSF);
    #pragma unroll
    for (int c = 0; c < 2; c++) {
        int i = threadIdx.x * 4 + c * 1024;
        float4 wv = *(const float4*)(w + i);
        float4 r;
        r.x = vals[c*4+0] * sc * wv.x; r.y = vals[c*4+1] * sc * wv.y;
        r.z = vals[c*4+2] * sc * wv.z; r.w = vals[c*4+3] * sc * wv.w;
        *(float4*)(o + (size_t)row * DIN + i) = r;
    }
}

// ---------------- causal depthwise conv (width 4) + bias + silu ----------------
__global__ void conv_k(const float* __restrict__ zx, const float* __restrict__ w,
                       const float* __restrict__ bias, float* __restrict__ out) {
    int idx = blockIdx.x * blockDim.x + threadIdx.x;
    if (idx >= T_ * CONVD) return;
    int c   = idx % CONVD;
    int tok = idx / CONVD;
    int l   = tok % L_;
    const float* base = zx + (size_t)tok * DPROJ + DIN + c;
    float w0 = w[c*4+0], w1 = w[c*4+1], w2 = w[c*4+2], w3 = w[c*4+3];
    float acc = bias[c];
    if (l >= 3) acc += base[-(ptrdiff_t)3*DPROJ] * w0;
    if (l >= 2) acc += base[-(ptrdiff_t)2*DPROJ] * w1;
    if (l >= 1) acc += base[-(ptrdiff_t)1*DPROJ] * w2;
    acc += base[0] * w3;
    out[idx] = siluf(acc);
}

// ---------------- selective scan (smem-staged, double buffered) ----------------
// grid = B_*NH*2 (p split in halves of 32); 256 threads.
// thread: pl = tid>>3 (0..31), n chunk = (tid&7)*16 .. +16. 16 states in regs.
// dt/dA precomputed once per block; B/C/x staged into smem in TS-step chunks.
__global__ void __launch_bounds__(256) scan_k(const float* __restrict__ cv,
                                              const float* __restrict__ zx,
                                              const float* __restrict__ dt_bias,
                                              const float* __restrict__ A_log,
                                              const float* __restrict__ Dv,
                                              float* __restrict__ y) {
    int bid = blockIdx.x;
    int ps  = bid & 1;
    int h   = (bid >> 1) & 31;
    int b   = bid >> 6;
    int tid = threadIdx.x;
    int pl  = tid >> 3;          // 0..31
    int nb  = (tid & 7) << 4;    // 0..112 step 16

    __shared__ float sDt[L_];            // softplus(dt + bias)
    __shared__ float sDA[L_];            // exp(dt * A)
    __shared__ float sB[2][TS][DS];
    __shared__ float sC[2][TS][DS];
    __shared__ float sX[2][TS][32];

    float Ah   = -__expf(A_log[h]);
    float Dh   = Dv[h];
    float bias = dt_bias[h];

    // precompute dt / dA for the whole sequence (once per block, not per thread-step)
    {
        const float* dptr = zx + (size_t)b * L_ * DPROJ + (DPROJ - NH) + h;
        for (int t = tid; t < L_; t += 256) {
            float v  = dptr[(size_t)t * DPROJ] + bias;
            float dt = (v > 20.f) ? v : log1pf(__expf(v));
            sDt[t] = dt;
            sDA[t] = __expf(dt * Ah);
        }
    }

    const float* bcbase = cv + (size_t)b * L_ * CONVD + DIN;          // B row (C right after)
    const float* xbase  = cv + (size_t)b * L_ * CONVD + h * HD + ps * 32;

    // stage chunk c into buffer buf (coalesced float4 loads)
    auto stage = [&](int c, int buf) {
        int t0 = c * TS;
        #pragma unroll
        for (int i = tid; i < TS * 64; i += 256) {       // 2 iters
            int t = i >> 6, j = i & 63;                  // j-th float4 of 256-float B|C row
            float4 v = *(const float4*)(bcbase + (size_t)(t0 + t) * CONVD + j * 4);
            if (j < 32) *(float4*)&sB[buf][t][j * 4] = v;
            else        *(float4*)&sC[buf][t][(j - 32) * 4] = v;
        }
        if (tid < TS * 8) {                              // x: TS x 32 floats
            int t = tid >> 3, j = tid & 7;
            *(float4*)&sX[buf][t][j * 4] =
                *(const float4*)(xbase + (size_t)(t0 + t) * CONVD + j * 4);
        }
    };

    stage(0, 0);
    __syncthreads();

    float hs[16];
    #pragma unroll
    for (int i = 0; i < 16; i++) hs[i] = 0.f;

    float* yptr = y + (size_t)b * L_ * DIN + h * HD + ps * 32 + pl;

    for (int c = 0; c < L_ / TS; c++) {
        int buf = c & 1;
        if (c + 1 < L_ / TS) stage(c + 1, buf ^ 1);      // loads overlap compute below

        #pragma unroll
        for (int tt = 0; tt < TS; tt++) {
            int t = c * TS + tt;
            float dt  = sDt[t];
            float dA  = sDA[t];
            float xv  = sX[buf][tt][pl];
            float dtx = dt * xv;
            const float* Bp = &sB[buf][tt][nb];
            const float* Cp = &sC[buf][tt][nb];
            float yp = 0.f;
            #pragma unroll
            for (int i = 0; i < 16; i += 4) {
                float4 bb = *(const float4*)(Bp + i);
                float4 cc = *(const float4*)(Cp + i);
                hs[i+0] = fmaf(hs[i+0], dA, dtx * bb.x); yp = fmaf(hs[i+0], cc.x, yp);
                hs[i+1] = fmaf(hs[i+1], dA, dtx * bb.y); yp = fmaf(hs[i+1], cc.y, yp);
                hs[i+2] = fmaf(hs[i+2], dA, dtx * bb.z); yp = fmaf(hs[i+2], cc.z, yp);
                hs[i+3] = fmaf(hs[i+3], dA, dtx * bb.w); yp = fmaf(hs[i+3], cc.w, yp);
            }
            yp += __shfl_xor_sync(0xffffffffu, yp, 1);
            yp += __shfl_xor_sync(0xffffffffu, yp, 2);
            yp += __shfl_xor_sync(0xffffffffu, yp, 4);
            if ((tid & 7) == 0)
                yptr[(size_t)t * DIN] = yp + Dh * xv;
        }
        __syncthreads();
    }
}

// ---------------- fp32 SIMT GEMM:  C[M,N] = A[M,K] * B[N,K]^T (+ Res) ----------------
// 128x128 block tile, BK=16, 256 threads, 8x8 per thread, register prefetch.
__global__ void __launch_bounds__(256) gemm_nt(const float* __restrict__ A,
                                               const float* __restrict__ Bm,
                                               const float* __restrict__ Res,
                                               float* __restrict__ C,
                                               int M, int N, int K) {
    __shared__ float As[16][132];
    __shared__ float Bs[16][132];

    int tid = threadIdx.x;
    int bm = blockIdx.y, bn = blockIdx.x;
    int tx = tid & 15, ty = tid >> 4;

    int lrow = tid >> 2;   // 0..63
    int lq   = tid & 3;    // 0..3 (k quad)

    const float* Ap = A + (size_t)(bm * 128 + lrow) * K + lq * 4;
    int n0 = bn * 128 + lrow;
    int n1 = n0 + 64;
    const float* Bp0 = Bm + (size_t)n0 * K + lq * 4;
    const float* Bp1 = Bm + (size_t)n1 * K + lq * 4;
    bool bv0 = n0 < N, bv1 = n1 < N;

    float acc[8][8];
    #pragma unroll
    for (int i = 0; i < 8; i++)
        #pragma unroll
        for (int j = 0; j < 8; j++) acc[i][j] = 0.f;

    const float4 fz = make_float4(0.f, 0.f, 0.f, 0.f);
    int nk = K >> 4;

    float4 pa0 = *(const float4*)(Ap);
    float4 pa1 = *(const float4*)(Ap + (size_t)64 * K);
    float4 pb0 = bv0 ? *(const float4*)(Bp0) : fz;
    float4 pb1 = bv1 ? *(const float4*)(Bp1) : fz;

    for (int kt = 0; kt < nk; kt++) {
        As[lq*4+0][lrow]    = pa0.x; As[lq*4+1][lrow]    = pa0.y;
        As[lq*4+2][lrow]    = pa0.z; As[lq*4+3][lrow]    = pa0.w;
        As[lq*4+0][lrow+64] = pa1.x; As[lq*4+1][lrow+64] = pa1.y;
        As[lq*4+2][lrow+64] = pa1.z; As[lq*4+3][lrow+64] = pa1.w;
        Bs[lq*4+0][lrow]    = pb0.x; Bs[lq*4+1][lrow]    = pb0.y;
        Bs[lq*4+2][lrow]    = pb0.z; Bs[lq*4+3][lrow]    = pb0.w;
        Bs[lq*4+0][lrow+64] = pb1.x; Bs[lq*4+1][lrow+64] = pb1.y;
        Bs[lq*4+2][lrow+64] = pb1.z; Bs[lq*4+3][lrow+64] = pb1.w;
        __syncthreads();

        if (kt + 1 < nk) {
            const float* a = Ap + (size_t)(kt + 1) * 16;
            pa0 = *(const float4*)(a);
            pa1 = *(const float4*)(a + (size_t)64 * K);
            pb0 = bv0 ? *(const float4*)(Bp0 + (size_t)(kt + 1) * 16) : fz;
            pb1 = bv1 ? *(const float4*)(Bp1 + (size_t)(kt + 1) * 16) : fz;
        }

        #pragma unroll
        for (int k = 0; k < 16; k++) {
            float4 a0 = *(const float4*)&As[k][ty * 4];
            float4 a1 = *(const float4*)&As[k][ty * 4 + 64];
            float4 b0 = *(const float4*)&Bs[k][tx * 4];
            float4 b1 = *(const float4*)&Bs[k][tx * 4 + 64];
            float av[8] = {a0.x, a0.y, a0.z, a0.w, a1.x, a1.y, a1.z, a1.w};
            float bw[8] = {b0.x, b0.y, b0.z, b0.w, b1.x, b1.y, b1.z, b1.w};
            #pragma unroll
            for (int i = 0; i < 8; i++)
                #pragma unroll
                for (int j = 0; j < 8; j++)
                    acc[i][j] = fmaf(av[i], bw[j], acc[i][j]);
        }
        __syncthreads();
    }

    #pragma unroll
    for (int i = 0; i < 8; i++) {
        int row = bm * 128 + ((i < 4) ? (ty * 4 + i) : (64 + ty * 4 + (i - 4)));
        float* Cr = C + (size_t)row * N;
        #pragma unroll
        for (int jh = 0; jh < 2; jh++) {
            int col = bn * 128 + tx * 4 + jh * 64;
            if (col < N) {
                float4 vv;
                vv.x = acc[i][jh*4+0]; vv.y = acc[i][jh*4+1];
                vv.z = acc[i][jh*4+2]; vv.w = acc[i][jh*4+3];
                if (Res) {
                    float4 r = *(const float4*)(Res + (size_t)row * N + col);
                    vv.x += r.x; vv.y += r.y; vv.z += r.z; vv.w += r.w;
                }
                *(float4*)(Cr + col) = vv;
            }
        }
    }
}

// ---------------- silu(gate) * up, in place into gate ----------------
__global__ void act_k(float* __restrict__ g, const float* __restrict__ u, int n) {
    int idx = blockIdx.x * blockDim.x + threadIdx.x;
    if (idx >= n) return;
    float x = g[idx];
    g[idx] = siluf(x) * u[idx];
}

// ---------------- host launcher ----------------
extern "C" void kernel_launch(void* const* d_in, const int* in_sizes, int n_in,
                              void* d_out, int out_size) {
    const float* hid        = (const float*)d_in[0];
    const float* norm_w     = (const float*)d_in[1];
    const float* in_proj_w  = (const float*)d_in[2];
    const float* conv_w     = (const float*)d_in[3];
    const float* conv_b     = (const float*)d_in[4];
    const float* dt_bias    = (const float*)d_in[5];
    const float* A_log      = (const float*)d_in[6];
    const float* Dv         = (const float*)d_in[7];
    const float* ssm_norm_w = (const float*)d_in[8];
    const float* out_proj_w = (const float*)d_in[9];
    const float* post_norm_w= (const float*)d_in[10];
    const float* gate_w     = (const float*)d_in[11];
    const float* up_w       = (const float*)d_in[12];
    const float* down_w     = (const float*)d_in[13];
    float* out = (float*)d_out;

    float *p_xn, *p_zx, *p_cv, *p_y, *p_yn, *p_x2, *p_hn, *p_gate, *p_up;
    cudaGetSymbolAddress((void**)&p_xn,   g_xn);
    cudaGetSymbolAddress((void**)&p_zx,   g_zx);
    cudaGetSymbolAddress((void**)&p_cv,   g_cv);
    cudaGetSymbolAddress((void**)&p_y,    g_y);
    cudaGetSymbolAddress((void**)&p_yn,   g_yn);
    cudaGetSymbolAddress((void**)&p_x2,   g_x2);
    cudaGetSymbolAddress((void**)&p_hn,   g_hn);
    cudaGetSymbolAddress((void**)&p_gate, g_gate);
    cudaGetSymbolAddress((void**)&p_up,   g_up);

    // 1. pre-norm
    rmsnorm1024_k<<<T_, 256>>>(hid, norm_w, p_xn);
    // 2. in_proj: [2048,4384] = xn @ W^T
    gemm_nt<<<dim3(35, 16), 256>>>(p_xn, in_proj_w, nullptr, p_zx, T_, DPROJ, DM);
    // 3. conv + silu
    conv_k<<<(T_ * CONVD + 255) / 256, 256>>>(p_zx, conv_w, conv_b, p_cv);
    // 4. selective scan
    scan_k<<<B_ * NH * 2, 256>>>(p_cv, p_zx, dt_bias, A_log, Dv, p_y);
    // 5. gated rmsnorm
    gated_norm_k<<<T_, 256>>>(p_y, p_zx, ssm_norm_w, p_yn);
    // 6. out_proj + residual (res = hidden_states)
    gemm_nt<<<dim3(8, 16), 256>>>(p_yn, out_proj_w, hid, p_x2, T_, DM, DIN);
    // 7. post-norm
    rmsnorm1024_k<<<T_, 256>>>(p_x2, post_norm_w, p_hn);
    // 8/9. gate & up projections
    gemm_nt<<<dim3(22, 16), 256>>>(p_hn, gate_w, nullptr, p_gate, T_, INTER, DM);
    gemm_nt<<<dim3(22, 16), 256>>>(p_hn, up_w, nullptr, p_up, T_, INTER, DM);
    // 10. silu(gate) * up
    act_k<<<(T_ * INTER + 255) / 256, 256>>>(p_gate, p_up, T_ * INTER);
    // 11. down projection + residual -> output
    gemm_nt<<<dim3(8, 16), 256>>>(p_gate, down_w, p_x2, out, T_, DM, INTER);
}